// round 3
// baseline (speedup 1.0000x reference)
#include <cuda_runtime.h>
#include <cuda_bf16.h>

// LightGCN on GB300 — CSR gather-only SpMM, v3.
//  - no init copy: layer-1 gathers straight from input embeddings,
//    epilogue seeds acc = input + sum
//  - CSR scatter packs (col,val) into one int2 (one 8B store per edge)
//  - edge stream loaded with __ldcs so the embedding tables stay L2-resident

#define N_USERS 100000
#define M_ITEMS 50000
#define NN      (N_USERS + M_ITEMS)   // 150000
#define DVEC    16                    // D=64 floats = 16 float4
#define INV_SCALE (1.0f / 16.0f)      // 1/(LAYERS+1)^2
#define NNZ_MAX 4000000
#define SCAN_B  1024
#define NBLK_SCAN ((NN + SCAN_B - 1) / SCAN_B)   // 147

// Static device scratch (allocation-free).
__device__ float4 g_emb[2][NN * DVEC];   // ping-pong layer buffers
__device__ float4 g_acc[NN * DVEC];      // running sum
__device__ int    g_rowptr[NN + 1];
__device__ int    g_wpos[NN];            // counter, then write cursor
__device__ int    g_excl[NN];
__device__ int    g_bsum[256];
__device__ int2   g_edge[NNZ_MAX];       // packed (col, val)

// ---------------------------------------------------------------------------
__global__ void lgcn_zero() {
    int i = blockIdx.x * blockDim.x + threadIdx.x;
    if (i < NN) g_wpos[i] = 0;
}

// ---------------------------------------------------------------------------
// CSR build
// ---------------------------------------------------------------------------
__global__ void lgcn_hist(const int* __restrict__ rows, int E) {
    int i = blockIdx.x * blockDim.x + threadIdx.x;
    if (i < E) atomicAdd(&g_wpos[__ldg(&rows[i])], 1);
}

__global__ void lgcn_scan1(int n) {
    __shared__ int s[SCAN_B];
    int i = blockIdx.x * SCAN_B + threadIdx.x;
    int v = (i < n) ? g_wpos[i] : 0;
    s[threadIdx.x] = v;
    __syncthreads();
    #pragma unroll
    for (int off = 1; off < SCAN_B; off <<= 1) {
        int t = (threadIdx.x >= off) ? s[threadIdx.x - off] : 0;
        __syncthreads();
        s[threadIdx.x] += t;
        __syncthreads();
    }
    int incl = s[threadIdx.x];
    if (i < n) g_excl[i] = incl - v;
    if (threadIdx.x == SCAN_B - 1) g_bsum[blockIdx.x] = incl;
}

__global__ void lgcn_scan2(int nb) {   // single block of 256
    __shared__ int s[256];
    int v = (threadIdx.x < nb) ? g_bsum[threadIdx.x] : 0;
    s[threadIdx.x] = v;
    __syncthreads();
    #pragma unroll
    for (int off = 1; off < 256; off <<= 1) {
        int t = (threadIdx.x >= off) ? s[threadIdx.x - off] : 0;
        __syncthreads();
        s[threadIdx.x] += t;
        __syncthreads();
    }
    if (threadIdx.x < nb) g_bsum[threadIdx.x] = s[threadIdx.x] - v;  // exclusive
}

__global__ void lgcn_scan3(int n, int E) {
    int i = blockIdx.x * blockDim.x + threadIdx.x;
    if (i >= n) return;
    int p = g_excl[i] + g_bsum[i / SCAN_B];
    g_rowptr[i] = p;
    g_wpos[i]   = p;
    if (i == 0) g_rowptr[n] = E;
}

__global__ void lgcn_scatter(const int*   __restrict__ rows,
                             const int*   __restrict__ cols,
                             const float* __restrict__ vals, int E) {
    int i = blockIdx.x * blockDim.x + threadIdx.x;
    if (i >= E) return;
    int r   = __ldg(&rows[i]);
    int pos = atomicAdd(&g_wpos[r], 1);
    g_edge[pos] = make_int2(__ldg(&cols[i]), __float_as_int(__ldg(&vals[i])));
}

// ---------------------------------------------------------------------------
// CSR SpMM: one warp per row. Two half-warps walk alternate edges; each lane
// owns one float4 component (coalesced 256B gather per edge).
// mode 0: layer1  — gather from inputs, acc = input + sum, write dst
// mode 1: middle  — gather g_emb[src], acc += sum, write dst
// mode 2: last    — gather g_emb[src], acc += sum, no dst write
// ---------------------------------------------------------------------------
__global__ void lgcn_spmm_csr(const float* __restrict__ uemb,
                              const float* __restrict__ iemb,
                              int src, int dst, int mode) {
    int w = (blockIdx.x * blockDim.x + threadIdx.x) >> 5;   // row
    if (w >= NN) return;
    int lane = threadIdx.x & 31;
    int half = lane >> 4;
    int comp = lane & 15;

    int start = __ldg(&g_rowptr[w]);
    int end   = __ldg(&g_rowptr[w + 1]);

    const float4* __restrict__ U = reinterpret_cast<const float4*>(uemb);
    const float4* __restrict__ I = reinterpret_cast<const float4*>(iemb);
    const float4* __restrict__ S = g_emb[src];

    float4 a = make_float4(0.f, 0.f, 0.f, 0.f);

    if (mode == 0) {
        #pragma unroll 4
        for (int e = start + half; e < end; e += 2) {
            int2  cv = __ldcs(&g_edge[e]);
            float v  = __int_as_float(cv.y);
            const float4* base = (cv.x < N_USERS) ? (U + cv.x * DVEC)
                                                  : (I + (cv.x - N_USERS) * DVEC);
            float4 x = __ldg(base + comp);
            a.x += v * x.x; a.y += v * x.y; a.z += v * x.z; a.w += v * x.w;
        }
    } else {
        #pragma unroll 4
        for (int e = start + half; e < end; e += 2) {
            int2  cv = __ldcs(&g_edge[e]);
            float v  = __int_as_float(cv.y);
            float4 x = __ldg(&S[cv.x * DVEC + comp]);
            a.x += v * x.x; a.y += v * x.y; a.z += v * x.z; a.w += v * x.w;
        }
    }

    // combine the two halves
    a.x += __shfl_xor_sync(0xFFFFFFFFu, a.x, 16);
    a.y += __shfl_xor_sync(0xFFFFFFFFu, a.y, 16);
    a.z += __shfl_xor_sync(0xFFFFFFFFu, a.z, 16);
    a.w += __shfl_xor_sync(0xFFFFFFFFu, a.w, 16);

    if (half == 0) {
        int o = w * DVEC + comp;
        if (mode != 2) g_emb[dst][o] = a;
        float4 c0;
        if (mode == 0) {
            c0 = (w < N_USERS) ? __ldg(U + w * DVEC + comp)
                               : __ldg(I + (w - N_USERS) * DVEC + comp);
        } else {
            c0 = g_acc[o];
        }
        c0.x += a.x; c0.y += a.y; c0.z += a.z; c0.w += a.w;
        g_acc[o] = c0;
    }
}

// ---------------------------------------------------------------------------
// dot: one warp per (user, item) pair
// ---------------------------------------------------------------------------
__global__ void lgcn_dot(const int* __restrict__ users,
                         const int* __restrict__ items,
                         float* __restrict__ out, int B) {
    int gt   = blockIdx.x * blockDim.x + threadIdx.x;
    int w    = gt >> 5;
    int lane = gt & 31;
    if (w >= B) return;

    int u  = __ldg(&users[w]);
    int it = __ldg(&items[w]);

    const float2* au = reinterpret_cast<const float2*>(&g_acc[u * DVEC]);
    const float2* ai = reinterpret_cast<const float2*>(&g_acc[(N_USERS + it) * DVEC]);

    float2 a = au[lane];
    float2 b = ai[lane];
    float s = a.x * b.x + a.y * b.y;

    #pragma unroll
    for (int off = 16; off > 0; off >>= 1)
        s += __shfl_xor_sync(0xFFFFFFFFu, s, off);

    if (lane == 0) out[w] = s * INV_SCALE;
}

// ---------------------------------------------------------------------------
// kernel_launch
// Inputs: 0 users(i32,B) 1 items(i32,B) 2 user_emb(f32) 3 item_emb(f32)
//         4 adj_rows(i32,NNZ) 5 adj_cols(i32,NNZ) 6 adj_vals(f32,NNZ)
// ---------------------------------------------------------------------------
extern "C" void kernel_launch(void* const* d_in, const int* in_sizes, int n_in,
                              void* d_out, int out_size) {
    const int*   users    = (const int*)  d_in[0];
    const int*   items    = (const int*)  d_in[1];
    const float* user_emb = (const float*)d_in[2];
    const float* item_emb = (const float*)d_in[3];
    const int*   rows     = (const int*)  d_in[4];
    const int*   cols     = (const int*)  d_in[5];
    const float* vals     = (const float*)d_in[6];
    float*       out      = (float*)      d_out;

    const int E = in_sizes[4];
    const int B = in_sizes[0];

    const int TPB   = 256;
    const int gE    = (E + TPB - 1) / TPB;
    const int gN    = (NN + TPB - 1) / TPB;
    const int gSpmm = (NN * 32 + TPB - 1) / TPB;
    const int gDot  = (B * 32 + TPB - 1) / TPB;

    // CSR build
    lgcn_zero<<<gN, TPB>>>();
    lgcn_hist<<<gE, TPB>>>(rows, E);
    lgcn_scan1<<<NBLK_SCAN, SCAN_B>>>(NN);
    lgcn_scan2<<<1, 256>>>(NBLK_SCAN);
    lgcn_scan3<<<gN, TPB>>>(NN, E);
    lgcn_scatter<<<gE, TPB>>>(rows, cols, vals, E);

    // 3 propagation layers (acc fused; layer1 reads inputs directly)
    lgcn_spmm_csr<<<gSpmm, TPB>>>(user_emb, item_emb, 0, 0, 0);  // inputs -> buf0
    lgcn_spmm_csr<<<gSpmm, TPB>>>(user_emb, item_emb, 0, 1, 1);  // buf0 -> buf1
    lgcn_spmm_csr<<<gSpmm, TPB>>>(user_emb, item_emb, 1, 0, 2);  // buf1 -> (acc only)

    lgcn_dot<<<gDot, TPB>>>(users, items, out, B);
}

// round 4
// speedup vs baseline: 1.1963x; 1.1963x over previous
#include <cuda_runtime.h>
#include <cuda_bf16.h>

// LightGCN on GB300 — CSR gather-only SpMM, v4 (v2 structure + safe wins).
//  - init fused into hist kernel (independent work, one launch)
//  - packed (col,val) int2 edges: one 8B store in scatter, one 8B __ldg in SpMM
//  - warp-shuffle scans (2 barriers instead of 20)

#define N_USERS 100000
#define M_ITEMS 50000
#define NN      (N_USERS + M_ITEMS)   // 150000
#define DVEC    16                    // D=64 floats = 16 float4
#define ELEMN   (NN * DVEC)           // 2.4M float4
#define INV_SCALE (1.0f / 16.0f)      // 1/(LAYERS+1)^2
#define NNZ_MAX 4000000
#define SCAN_B  1024
#define NBLK_SCAN ((NN + SCAN_B - 1) / SCAN_B)   // 147

// Static device scratch (allocation-free).
__device__ float4 g_emb[2][ELEMN];    // ping-pong layer buffers
__device__ float4 g_acc[ELEMN];       // running sum
__device__ int    g_rowptr[NN + 1];
__device__ int    g_wpos[NN];         // counter, then write cursor
__device__ int    g_excl[NN];
__device__ int    g_bsum[256];
__device__ int2   g_edge[NNZ_MAX];    // packed (col, val)

// ---------------------------------------------------------------------------
__global__ void lgcn_zero() {
    int i = blockIdx.x * blockDim.x + threadIdx.x;
    if (i < NN) g_wpos[i] = 0;
}

// ---------------------------------------------------------------------------
// init (table copy) + histogram, fused: independent work, overlapped.
// Grid covers ELEMN threads; edges handled grid-stride.
// ---------------------------------------------------------------------------
__global__ void lgcn_init_hist(const float* __restrict__ user_emb,
                               const float* __restrict__ item_emb,
                               const int*   __restrict__ rows, int E) {
    int i = blockIdx.x * blockDim.x + threadIdx.x;
    if (i < ELEMN) {
        float4 v;
        if (i < N_USERS * DVEC) {
            v = reinterpret_cast<const float4*>(user_emb)[i];
        } else {
            v = reinterpret_cast<const float4*>(item_emb)[i - N_USERS * DVEC];
        }
        g_emb[0][i] = v;
        g_acc[i]    = v;
    }
    for (int e = i; e < E; e += ELEMN)
        atomicAdd(&g_wpos[__ldg(&rows[e])], 1);
}

// ---------------------------------------------------------------------------
// warp-shuffle scans
// ---------------------------------------------------------------------------
__device__ __forceinline__ int warp_incl_scan(int v) {
    int lane = threadIdx.x & 31;
    #pragma unroll
    for (int o = 1; o < 32; o <<= 1) {
        int t = __shfl_up_sync(0xFFFFFFFFu, v, o);
        if (lane >= o) v += t;
    }
    return v;
}

__global__ void lgcn_scan1(int n) {
    __shared__ int wsum[32];
    int i = blockIdx.x * SCAN_B + threadIdx.x;
    int v = (i < n) ? g_wpos[i] : 0;
    int incl = warp_incl_scan(v);
    int wid = threadIdx.x >> 5, lane = threadIdx.x & 31;
    if (lane == 31) wsum[wid] = incl;
    __syncthreads();
    if (wid == 0) {
        int s = wsum[lane];
        s = warp_incl_scan(s);
        wsum[lane] = s;
    }
    __syncthreads();
    int off = wid ? wsum[wid - 1] : 0;
    incl += off;
    if (i < n) g_excl[i] = incl - v;
    if (threadIdx.x == SCAN_B - 1) g_bsum[blockIdx.x] = incl;
}

__global__ void lgcn_scan2(int nb) {   // single block of 256, nb <= 256
    __shared__ int wsum[8];
    int v = (threadIdx.x < nb) ? g_bsum[threadIdx.x] : 0;
    int incl = warp_incl_scan(v);
    int wid = threadIdx.x >> 5, lane = threadIdx.x & 31;
    if (lane == 31) wsum[wid] = incl;
    __syncthreads();
    if (wid == 0 && lane < 8) {
        int s = wsum[lane];
        #pragma unroll
        for (int o = 1; o < 8; o <<= 1) {
            int t = __shfl_up_sync(0x000000FFu, s, o);
            if (lane >= o) s += t;
        }
        wsum[lane] = s;
    }
    __syncthreads();
    int off = wid ? wsum[wid - 1] : 0;
    if (threadIdx.x < nb) g_bsum[threadIdx.x] = incl + off - v;  // exclusive
}

__global__ void lgcn_scan3(int n, int E) {
    int i = blockIdx.x * blockDim.x + threadIdx.x;
    if (i >= n) return;
    int p = g_excl[i] + g_bsum[i / SCAN_B];
    g_rowptr[i] = p;
    g_wpos[i]   = p;
    if (i == 0) g_rowptr[n] = E;
}

// ---------------------------------------------------------------------------
__global__ void lgcn_scatter(const int*   __restrict__ rows,
                             const int*   __restrict__ cols,
                             const float* __restrict__ vals, int E) {
    int i = blockIdx.x * blockDim.x + threadIdx.x;
    if (i >= E) return;
    int r   = __ldg(&rows[i]);
    int pos = atomicAdd(&g_wpos[r], 1);
    g_edge[pos] = make_int2(__ldg(&cols[i]), __float_as_int(__ldg(&vals[i])));
}

// ---------------------------------------------------------------------------
// CSR SpMM: one warp per row. Two half-warps walk alternate edges; each lane
// owns one float4 component (coalesced 256B gather per edge).
// ---------------------------------------------------------------------------
__global__ void lgcn_spmm_csr(int src, int dst, int writeDst) {
    int w = (blockIdx.x * blockDim.x + threadIdx.x) >> 5;   // row
    if (w >= NN) return;
    int lane = threadIdx.x & 31;
    int half = lane >> 4;
    int comp = lane & 15;

    int start = __ldg(&g_rowptr[w]);
    int end   = __ldg(&g_rowptr[w + 1]);

    const float4* __restrict__ S = g_emb[src];
    float4 a = make_float4(0.f, 0.f, 0.f, 0.f);

    #pragma unroll 4
    for (int e = start + half; e < end; e += 2) {
        int2  cv = __ldg(&g_edge[e]);
        float v  = __int_as_float(cv.y);
        float4 x = __ldg(&S[cv.x * DVEC + comp]);
        a.x += v * x.x; a.y += v * x.y; a.z += v * x.z; a.w += v * x.w;
    }

    // combine the two halves
    a.x += __shfl_xor_sync(0xFFFFFFFFu, a.x, 16);
    a.y += __shfl_xor_sync(0xFFFFFFFFu, a.y, 16);
    a.z += __shfl_xor_sync(0xFFFFFFFFu, a.z, 16);
    a.w += __shfl_xor_sync(0xFFFFFFFFu, a.w, 16);

    if (half == 0) {
        int o = w * DVEC + comp;
        if (writeDst) g_emb[dst][o] = a;
        float4 c0 = g_acc[o];
        c0.x += a.x; c0.y += a.y; c0.z += a.z; c0.w += a.w;
        g_acc[o] = c0;
    }
}

// ---------------------------------------------------------------------------
// dot: one warp per (user, item) pair
// ---------------------------------------------------------------------------
__global__ void lgcn_dot(const int* __restrict__ users,
                         const int* __restrict__ items,
                         float* __restrict__ out, int B) {
    int gt   = blockIdx.x * blockDim.x + threadIdx.x;
    int w    = gt >> 5;
    int lane = gt & 31;
    if (w >= B) return;

    int u  = __ldg(&users[w]);
    int it = __ldg(&items[w]);

    const float2* au = reinterpret_cast<const float2*>(&g_acc[u * DVEC]);
    const float2* ai = reinterpret_cast<const float2*>(&g_acc[(N_USERS + it) * DVEC]);

    float2 a = au[lane];
    float2 b = ai[lane];
    float s = a.x * b.x + a.y * b.y;

    #pragma unroll
    for (int off = 16; off > 0; off >>= 1)
        s += __shfl_xor_sync(0xFFFFFFFFu, s, off);

    if (lane == 0) out[w] = s * INV_SCALE;
}

// ---------------------------------------------------------------------------
// kernel_launch
// Inputs: 0 users(i32,B) 1 items(i32,B) 2 user_emb(f32) 3 item_emb(f32)
//         4 adj_rows(i32,NNZ) 5 adj_cols(i32,NNZ) 6 adj_vals(f32,NNZ)
// ---------------------------------------------------------------------------
extern "C" void kernel_launch(void* const* d_in, const int* in_sizes, int n_in,
                              void* d_out, int out_size) {
    const int*   users    = (const int*)  d_in[0];
    const int*   items    = (const int*)  d_in[1];
    const float* user_emb = (const float*)d_in[2];
    const float* item_emb = (const float*)d_in[3];
    const int*   rows     = (const int*)  d_in[4];
    const int*   cols     = (const int*)  d_in[5];
    const float* vals     = (const float*)d_in[6];
    float*       out      = (float*)      d_out;

    const int E = in_sizes[4];
    const int B = in_sizes[0];

    const int TPB   = 256;
    const int gInit = (ELEMN + TPB - 1) / TPB;
    const int gE    = (E + TPB - 1) / TPB;
    const int gN    = (NN + TPB - 1) / TPB;
    const int gSpmm = (NN * 32 + TPB - 1) / TPB;
    const int gDot  = (B * 32 + TPB - 1) / TPB;

    // CSR build + table init
    lgcn_zero<<<gN, TPB>>>();
    lgcn_init_hist<<<gInit, TPB>>>(user_emb, item_emb, rows, E);
    lgcn_scan1<<<NBLK_SCAN, SCAN_B>>>(NN);
    lgcn_scan2<<<1, 256>>>(NBLK_SCAN);
    lgcn_scan3<<<gN, TPB>>>(NN, E);
    lgcn_scatter<<<gE, TPB>>>(rows, cols, vals, E);

    // 3 propagation layers (acc fused into epilogue)
    lgcn_spmm_csr<<<gSpmm, TPB>>>(0, 1, 1);
    lgcn_spmm_csr<<<gSpmm, TPB>>>(1, 0, 1);
    lgcn_spmm_csr<<<gSpmm, TPB>>>(0, 1, 0);   // last layer: acc only

    lgcn_dot<<<gDot, TPB>>>(users, items, out, B);
}

// round 5
// speedup vs baseline: 1.3745x; 1.1490x over previous
#include <cuda_runtime.h>
#include <cuda_fp16.h>
#include <cuda_bf16.h>

// LightGCN on GB300 — CSR gather-only SpMM, v5.
// v4 + ONE change: ping-pong layer sources stored as fp16 (128B/row instead
// of 256B), halving the dominant L2 gather traffic. All accumulation, the
// running acc, and the dot stay fp32.

#define N_USERS 100000
#define M_ITEMS 50000
#define NN      (N_USERS + M_ITEMS)   // 150000
#define DVEC    16                    // D=64 floats = 16 float4
#define HVEC    16                    // D=64 halfs  = 16 uint2 (4 halves each)
#define ELEMN   (NN * DVEC)           // 2.4M float4
#define INV_SCALE (1.0f / 16.0f)      // 1/(LAYERS+1)^2
#define NNZ_MAX 4000000
#define SCAN_B  1024
#define NBLK_SCAN ((NN + SCAN_B - 1) / SCAN_B)   // 147

// Static device scratch (allocation-free).
__device__ uint2  g_h[2][NN * HVEC];  // fp16 ping-pong layer buffers (19.2MB ea)
__device__ float4 g_acc[ELEMN];       // fp32 running sum
__device__ int    g_rowptr[NN + 1];
__device__ int    g_wpos[NN];         // counter, then write cursor
__device__ int    g_excl[NN];
__device__ int    g_bsum[256];
__device__ int2   g_edge[NNZ_MAX];    // packed (col, val)

// pack float4 -> 4 halves in uint2
__device__ __forceinline__ uint2 pack_h4(float4 a) {
    __half2 p0 = __floats2half2_rn(a.x, a.y);
    __half2 p1 = __floats2half2_rn(a.z, a.w);
    uint2 u;
    u.x = *reinterpret_cast<unsigned*>(&p0);
    u.y = *reinterpret_cast<unsigned*>(&p1);
    return u;
}

// ---------------------------------------------------------------------------
__global__ void lgcn_zero() {
    int i = blockIdx.x * blockDim.x + threadIdx.x;
    if (i < NN) g_wpos[i] = 0;
}

// ---------------------------------------------------------------------------
// init (table copy: fp32 acc + fp16 layer source) + histogram, fused.
// ---------------------------------------------------------------------------
__global__ void lgcn_init_hist(const float* __restrict__ user_emb,
                               const float* __restrict__ item_emb,
                               const int*   __restrict__ rows, int E) {
    int i = blockIdx.x * blockDim.x + threadIdx.x;
    if (i < ELEMN) {
        float4 v;
        if (i < N_USERS * DVEC) {
            v = reinterpret_cast<const float4*>(user_emb)[i];
        } else {
            v = reinterpret_cast<const float4*>(item_emb)[i - N_USERS * DVEC];
        }
        g_acc[i]  = v;
        g_h[0][i] = pack_h4(v);
    }
    for (int e = i; e < E; e += ELEMN)
        atomicAdd(&g_wpos[__ldg(&rows[e])], 1);
}

// ---------------------------------------------------------------------------
// warp-shuffle scans
// ---------------------------------------------------------------------------
__device__ __forceinline__ int warp_incl_scan(int v) {
    int lane = threadIdx.x & 31;
    #pragma unroll
    for (int o = 1; o < 32; o <<= 1) {
        int t = __shfl_up_sync(0xFFFFFFFFu, v, o);
        if (lane >= o) v += t;
    }
    return v;
}

__global__ void lgcn_scan1(int n) {
    __shared__ int wsum[32];
    int i = blockIdx.x * SCAN_B + threadIdx.x;
    int v = (i < n) ? g_wpos[i] : 0;
    int incl = warp_incl_scan(v);
    int wid = threadIdx.x >> 5, lane = threadIdx.x & 31;
    if (lane == 31) wsum[wid] = incl;
    __syncthreads();
    if (wid == 0) {
        int s = wsum[lane];
        s = warp_incl_scan(s);
        wsum[lane] = s;
    }
    __syncthreads();
    int off = wid ? wsum[wid - 1] : 0;
    incl += off;
    if (i < n) g_excl[i] = incl - v;
    if (threadIdx.x == SCAN_B - 1) g_bsum[blockIdx.x] = incl;
}

__global__ void lgcn_scan2(int nb) {   // single block of 256, nb <= 256
    __shared__ int wsum[8];
    int v = (threadIdx.x < nb) ? g_bsum[threadIdx.x] : 0;
    int incl = warp_incl_scan(v);
    int wid = threadIdx.x >> 5, lane = threadIdx.x & 31;
    if (lane == 31) wsum[wid] = incl;
    __syncthreads();
    if (wid == 0 && lane < 8) {
        int s = wsum[lane];
        #pragma unroll
        for (int o = 1; o < 8; o <<= 1) {
            int t = __shfl_up_sync(0x000000FFu, s, o);
            if (lane >= o) s += t;
        }
        wsum[lane] = s;
    }
    __syncthreads();
    int off = wid ? wsum[wid - 1] : 0;
    if (threadIdx.x < nb) g_bsum[threadIdx.x] = incl + off - v;  // exclusive
}

__global__ void lgcn_scan3(int n, int E) {
    int i = blockIdx.x * blockDim.x + threadIdx.x;
    if (i >= n) return;
    int p = g_excl[i] + g_bsum[i / SCAN_B];
    g_rowptr[i] = p;
    g_wpos[i]   = p;
    if (i == 0) g_rowptr[n] = E;
}

// ---------------------------------------------------------------------------
__global__ void lgcn_scatter(const int*   __restrict__ rows,
                             const int*   __restrict__ cols,
                             const float* __restrict__ vals, int E) {
    int i = blockIdx.x * blockDim.x + threadIdx.x;
    if (i >= E) return;
    int r   = __ldg(&rows[i]);
    int pos = atomicAdd(&g_wpos[r], 1);
    g_edge[pos] = make_int2(__ldg(&cols[i]), __float_as_int(__ldg(&vals[i])));
}

// ---------------------------------------------------------------------------
// CSR SpMM: one warp per row. Two half-warps walk alternate edges; each lane
// owns 4 half components (one uint2, coalesced 128B gather per edge).
// fp32 accumulation; epilogue writes fp16 dst (if needed) + fp32 acc update.
// ---------------------------------------------------------------------------
__global__ void lgcn_spmm_csr(int src, int dst, int writeDst) {
    int w = (blockIdx.x * blockDim.x + threadIdx.x) >> 5;   // row
    if (w >= NN) return;
    int lane = threadIdx.x & 31;
    int half = lane >> 4;
    int comp = lane & 15;

    int start = __ldg(&g_rowptr[w]);
    int end   = __ldg(&g_rowptr[w + 1]);

    const uint2* __restrict__ S = g_h[src];
    float4 a = make_float4(0.f, 0.f, 0.f, 0.f);

    #pragma unroll 4
    for (int e = start + half; e < end; e += 2) {
        int2  cv = __ldg(&g_edge[e]);
        float v  = __int_as_float(cv.y);
        uint2 h  = __ldg(&S[cv.x * HVEC + comp]);
        __half2 h0 = *reinterpret_cast<__half2*>(&h.x);
        __half2 h1 = *reinterpret_cast<__half2*>(&h.y);
        float2 f0 = __half22float2(h0);
        float2 f1 = __half22float2(h1);
        a.x += v * f0.x; a.y += v * f0.y; a.z += v * f1.x; a.w += v * f1.y;
    }

    // combine the two halves
    a.x += __shfl_xor_sync(0xFFFFFFFFu, a.x, 16);
    a.y += __shfl_xor_sync(0xFFFFFFFFu, a.y, 16);
    a.z += __shfl_xor_sync(0xFFFFFFFFu, a.z, 16);
    a.w += __shfl_xor_sync(0xFFFFFFFFu, a.w, 16);

    if (half == 0) {
        int o = w * DVEC + comp;
        if (writeDst) g_h[dst][o] = pack_h4(a);
        float4 c0 = g_acc[o];
        c0.x += a.x; c0.y += a.y; c0.z += a.z; c0.w += a.w;
        g_acc[o] = c0;
    }
}

// ---------------------------------------------------------------------------
// dot: one warp per (user, item) pair (fp32 path, unchanged)
// ---------------------------------------------------------------------------
__global__ void lgcn_dot(const int* __restrict__ users,
                         const int* __restrict__ items,
                         float* __restrict__ out, int B) {
    int gt   = blockIdx.x * blockDim.x + threadIdx.x;
    int w    = gt >> 5;
    int lane = gt & 31;
    if (w >= B) return;

    int u  = __ldg(&users[w]);
    int it = __ldg(&items[w]);

    const float2* au = reinterpret_cast<const float2*>(&g_acc[u * DVEC]);
    const float2* ai = reinterpret_cast<const float2*>(&g_acc[(N_USERS + it) * DVEC]);

    float2 a = au[lane];
    float2 b = ai[lane];
    float s = a.x * b.x + a.y * b.y;

    #pragma unroll
    for (int off = 16; off > 0; off >>= 1)
        s += __shfl_xor_sync(0xFFFFFFFFu, s, off);

    if (lane == 0) out[w] = s * INV_SCALE;
}

// ---------------------------------------------------------------------------
// kernel_launch
// Inputs: 0 users(i32,B) 1 items(i32,B) 2 user_emb(f32) 3 item_emb(f32)
//         4 adj_rows(i32,NNZ) 5 adj_cols(i32,NNZ) 6 adj_vals(f32,NNZ)
// ---------------------------------------------------------------------------
extern "C" void kernel_launch(void* const* d_in, const int* in_sizes, int n_in,
                              void* d_out, int out_size) {
    const int*   users    = (const int*)  d_in[0];
    const int*   items    = (const int*)  d_in[1];
    const float* user_emb = (const float*)d_in[2];
    const float* item_emb = (const float*)d_in[3];
    const int*   rows     = (const int*)  d_in[4];
    const int*   cols     = (const int*)  d_in[5];
    const float* vals     = (const float*)d_in[6];
    float*       out      = (float*)      d_out;

    const int E = in_sizes[4];
    const int B = in_sizes[0];

    const int TPB   = 256;
    const int gInit = (ELEMN + TPB - 1) / TPB;
    const int gE    = (E + TPB - 1) / TPB;
    const int gN    = (NN + TPB - 1) / TPB;
    const int gSpmm = (NN * 32 + TPB - 1) / TPB;
    const int gDot  = (B * 32 + TPB - 1) / TPB;

    // CSR build + table init
    lgcn_zero<<<gN, TPB>>>();
    lgcn_init_hist<<<gInit, TPB>>>(user_emb, item_emb, rows, E);
    lgcn_scan1<<<NBLK_SCAN, SCAN_B>>>(NN);
    lgcn_scan2<<<1, 256>>>(NBLK_SCAN);
    lgcn_scan3<<<gN, TPB>>>(NN, E);
    lgcn_scatter<<<gE, TPB>>>(rows, cols, vals, E);

    // 3 propagation layers (acc fused into epilogue)
    lgcn_spmm_csr<<<gSpmm, TPB>>>(0, 1, 1);
    lgcn_spmm_csr<<<gSpmm, TPB>>>(1, 0, 1);
    lgcn_spmm_csr<<<gSpmm, TPB>>>(0, 1, 0);   // last layer: acc only

    lgcn_dot<<<gDot, TPB>>>(users, items, out, B);
}